// round 13
// baseline (speedup 1.0000x reference)
#include <cuda_runtime.h>
#include <cuda_bf16.h>

// Problem shape (fixed by reference)
#define VOCAB   1000000
#define EMB     64
#define BATCH   4096
#define SLOTS   26
#define MAX_NNZ 10

static constexpr int PAIRS = BATCH * SLOTS;          // 106,496 (b,s) pairs
static constexpr int LANES_PER_PAIR = 16;            // 16 threads x float4 = 64 floats
static constexpr int THREADS = 256;

// sm_103 quirk: bare ".L2::evict_last" is only encodable on 256-bit loads.
// For 128-bit loads the route is createpolicy + ".L2::cache_hint" (same
// semantics, policy in a b64 register). Policy is created once per thread.
__device__ __forceinline__ unsigned long long mk_evict_last_policy()
{
    unsigned long long pol;
    asm("createpolicy.fractional.L2::evict_last.b64 %0, 1.0;" : "=l"(pol));
    return pol;
}

// Predicated float4 gather with L2 evict_last cache hint.
// The unique table footprint (~471K rows = 121MB) is just under the 126MB L2,
// and the harness graph-replays the identical launch -> pinning table lines
// lets them survive across replays, turning DRAM gathers into L2 hits.
// Predicate lives inside the asm (setp + @p ld): no BSSY/BSYNC divergence,
// zero-init survives masked lanes.
__device__ __forceinline__ float4 ld_table_evict_last(const float* p, int pred,
                                                      unsigned long long pol)
{
    float4 v = make_float4(0.f, 0.f, 0.f, 0.f);
    asm volatile(
        "{\n\t"
        ".reg .pred p;\n\t"
        "setp.ne.s32 p, %5, 0;\n\t"
        "@p ld.global.nc.L2::cache_hint.v4.f32 {%0,%1,%2,%3}, [%4], %6;\n\t"
        "}"
        : "+f"(v.x), "+f"(v.y), "+f"(v.z), "+f"(v.w)
        : "l"(p), "r"(pred), "l"(pol));
    return v;
}

// One (batch,slot) pair per 16-thread group; each lane owns one float4 of the
// 64-dim vector -> each row gather is a fully coalesced 256B read.
// Structure = R7 best (2 waves x 5 deep, default launch bounds, ~32 regs,
// occ ~80%): the R9/R11 occupancy-for-MLP trade measured neutral-to-worse.
__global__ __launch_bounds__(THREADS)
void emb_lookup_kernel(const int* __restrict__ keys,
                       const int* __restrict__ mask,
                       const float* __restrict__ table,
                       float* __restrict__ out)
{
    const int gid  = blockIdx.x * THREADS + threadIdx.x;
    const int pair = gid >> 4;          // (b*SLOTS + s)
    const int lane = gid & 15;          // which float4 of the 64-dim vector
    if (pair >= PAIRS) return;

    const unsigned long long pol = mk_evict_last_policy();
    const int base = pair * MAX_NNZ;

    // Vectorized key/mask preload: 5x int2 each (40B per pair, 8B aligned).
    const int2* kp = reinterpret_cast<const int2*>(keys + base);
    const int2* mp = reinterpret_cast<const int2*>(mask + base);
    int km[MAX_NNZ];   // key
    int mm_[MAX_NNZ];  // raw mask word (nonzero = valid; covers i32 and f32 bools)
#pragma unroll
    for (int j = 0; j < 5; j++) {
        const int2 kk = kp[j];
        const int2 mv = mp[j];
        km[2*j]   = kk.x;  km[2*j+1] = kk.y;
        mm_[2*j]  = mv.x;  mm_[2*j+1] = mv.y;
    }

    int cnt = 0;
#pragma unroll
    for (int n = 0; n < MAX_NNZ; n++) cnt += (mm_[n] != 0) ? 1 : 0;

    float4 acc = make_float4(0.f, 0.f, 0.f, 0.f);

    // Two waves of 5 batched predicated gathers (fits the 32-reg budget that
    // gave the best measured config).
#pragma unroll
    for (int w = 0; w < 2; w++) {
        float4 v[5];
#pragma unroll
        for (int j = 0; j < 5; j++) {
            const int n = w * 5 + j;
            v[j] = ld_table_evict_last(
                table + (size_t)km[n] * EMB + lane * 4, mm_[n], pol);
        }
#pragma unroll
        for (int j = 0; j < 5; j++) {
            acc.x += v[j].x; acc.y += v[j].y;
            acc.z += v[j].z; acc.w += v[j].w;
        }
    }

    const float inv = 1.0f / (float)(cnt > 0 ? cnt : 1);
    float4 r;
    r.x = acc.x * inv;
    r.y = acc.y * inv;
    r.z = acc.z * inv;
    r.w = acc.w * inv;

    // Streaming store: evict-first, keep the table's L2 resident set intact.
    __stcs(reinterpret_cast<float4*>(out + (size_t)pair * EMB + lane * 4), r);
}

extern "C" void kernel_launch(void* const* d_in, const int* in_sizes, int n_in,
                              void* d_out, int out_size)
{
    const int*   keys  = (const int*)d_in[0];
    const int*   mask  = (const int*)d_in[1];
    const float* table = (const float*)d_in[2];
    float*       out   = (float*)d_out;

    const int total_threads = PAIRS * LANES_PER_PAIR;
    const int blocks = (total_threads + THREADS - 1) / THREADS;
    emb_lookup_kernel<<<blocks, THREADS>>>(keys, mask, table, out);
}

// round 14
// speedup vs baseline: 1.0072x; 1.0072x over previous
#include <cuda_runtime.h>
#include <cuda_bf16.h>

// Problem shape (fixed by reference)
#define VOCAB   1000000
#define EMB     64
#define BATCH   4096
#define SLOTS   26
#define MAX_NNZ 10

static constexpr int PAIRS = BATCH * SLOTS;          // 106,496 (b,s) pairs
static constexpr int LANES_PER_PAIR = 8;             // 8 threads x 8 floats = 64 dims
static constexpr int THREADS = 256;

// Predicated 256-bit (v8.b32) table gather. sm_103 supports 256-bit LDG;
// 32B per lane doubles outstanding BYTES per in-flight load at the same
// register/MLP budget — feeding the DRAM queues harder than more-but-narrower
// loads (R11 showed warp/depth trades are zero-sum; request width is not).
// Predicate inside the asm: no BSSY/BSYNC, zero-init survives masked rows.
__device__ __forceinline__ void ld_table_v8(const float* p, int pred, float* v)
{
    asm volatile(
        "{\n\t"
        ".reg .pred p;\n\t"
        "setp.ne.s32 p, %9, 0;\n\t"
        "@p ld.global.nc.v8.f32 {%0,%1,%2,%3,%4,%5,%6,%7}, [%8];\n\t"
        "}"
        : "+f"(v[0]), "+f"(v[1]), "+f"(v[2]), "+f"(v[3]),
          "+f"(v[4]), "+f"(v[5]), "+f"(v[6]), "+f"(v[7])
        : "l"(p), "r"(pred));
}

// One (batch,slot) pair per 8-thread group; each lane owns 8 embedding dims
// (one 32B chunk) -> each row gather is a fully coalesced 256B read issued as
// a single v8 load per lane. Keys/mask preloaded as int2 (40B, 8B-aligned).
// No L2 policy hints: R13 proved evict_last pinning regresses steady-state
// (121MB set + 27MB output > 126MB L2; hints only reorder the thrash).
__global__ __launch_bounds__(THREADS)
void emb_lookup_kernel(const int* __restrict__ keys,
                       const int* __restrict__ mask,
                       const float* __restrict__ table,
                       float* __restrict__ out)
{
    const int gid  = blockIdx.x * THREADS + threadIdx.x;
    const int pair = gid >> 3;          // (b*SLOTS + s)
    const int lane = gid & 7;           // which 8-float chunk of the 64-dim row
    if (pair >= PAIRS) return;

    const int base = pair * MAX_NNZ;

    const int2* kp = reinterpret_cast<const int2*>(keys + base);
    const int2* mp = reinterpret_cast<const int2*>(mask + base);
    int km[MAX_NNZ];
    int mm_[MAX_NNZ];
#pragma unroll
    for (int j = 0; j < 5; j++) {
        const int2 kk = kp[j];
        const int2 mv = mp[j];
        km[2*j]   = kk.x;  km[2*j+1] = kk.y;
        mm_[2*j]  = mv.x;  mm_[2*j+1] = mv.y;   // nonzero = valid (i32 or f32 bool)
    }

    int cnt = 0;
#pragma unroll
    for (int n = 0; n < MAX_NNZ; n++) cnt += (mm_[n] != 0) ? 1 : 0;

    float acc[8];
#pragma unroll
    for (int d = 0; d < 8; d++) acc[d] = 0.f;

    // Two waves of 5 batched predicated v8 gathers: up to 5 x 32B outstanding
    // per thread before the reduction consumes anything.
#pragma unroll
    for (int w = 0; w < 2; w++) {
        float v[5][8];
#pragma unroll
        for (int j = 0; j < 5; j++) {
#pragma unroll
            for (int d = 0; d < 8; d++) v[j][d] = 0.f;
            const int n = w * 5 + j;
            ld_table_v8(table + (size_t)km[n] * EMB + lane * 8, mm_[n], v[j]);
        }
#pragma unroll
        for (int j = 0; j < 5; j++)
#pragma unroll
            for (int d = 0; d < 8; d++) acc[d] += v[j][d];
    }

    const float inv = 1.0f / (float)(cnt > 0 ? cnt : 1);
    float4 r0, r1;
    r0.x = acc[0] * inv; r0.y = acc[1] * inv; r0.z = acc[2] * inv; r0.w = acc[3] * inv;
    r1.x = acc[4] * inv; r1.y = acc[5] * inv; r1.z = acc[6] * inv; r1.w = acc[7] * inv;

    // Streaming stores: evict-first, keep L2 capacity for table lines.
    float4* o = reinterpret_cast<float4*>(out + (size_t)pair * EMB + lane * 8);
    __stcs(o,     r0);
    __stcs(o + 1, r1);
}

extern "C" void kernel_launch(void* const* d_in, const int* in_sizes, int n_in,
                              void* d_out, int out_size)
{
    const int*   keys  = (const int*)d_in[0];
    const int*   mask  = (const int*)d_in[1];
    const float* table = (const float*)d_in[2];
    float*       out   = (float*)d_out;

    const int total_threads = PAIRS * LANES_PER_PAIR;
    const int blocks = (total_threads + THREADS - 1) / THREADS;
    emb_lookup_kernel<<<blocks, THREADS>>>(keys, mask, table, out);
}